// round 6
// baseline (speedup 1.0000x reference)
#include <cuda_runtime.h>
#include <math.h>
#include <stdint.h>

// Problem constants
#define BB 2
#define LL 1024
#define HH 256
#define NHEAD 8
#define DHEAD 32
#define FFD 1024
#define NLAYER 2
#define RELN 100
#define EPSLN 1e-5f
// 1/sqrt(32) * log2(e)  (exp done in base 2)
#define QSCALE (0.17677669529663687f * 1.4426950408889634f)

#define ROWS (BB*LL)          // 2048

// ---------------- scratch (static device memory; no allocations allowed) ----
__device__ float g_qb[ROWS*HH];
__device__ float g_kb[ROWS*HH];
__device__ float g_vb[ROWS*HH];
__device__ float g_ab[ROWS*HH];
__device__ float g_yb[ROWS*HH];
__device__ float g_xb[ROWS*HH];
__device__ float g_fb[ROWS*FFD];

__device__ __forceinline__ float ex2f(float x) {
    float y;
    asm("ex2.approx.ftz.f32 %0, %1;" : "=f"(y) : "f"(x));
    return y;
}

__device__ __forceinline__ float tf32r(float x) {
    float y;
    asm("cvt.rna.tf32.f32 %0, %1;" : "=f"(y) : "f"(x));
    return y;
}

__device__ __forceinline__ void mma_tf32(
    float& c0, float& c1, float& c2, float& c3,
    uint32_t a0, uint32_t a1, uint32_t a2, uint32_t a3,
    uint32_t b0, uint32_t b1)
{
    asm volatile(
        "mma.sync.aligned.m16n8k8.row.col.f32.tf32.tf32.f32 "
        "{%0,%1,%2,%3}, {%4,%5,%6,%7}, {%8,%9}, {%0,%1,%2,%3};"
        : "+f"(c0), "+f"(c1), "+f"(c2), "+f"(c3)
        : "r"(a0), "r"(a1), "r"(a2), "r"(a3), "r"(b0), "r"(b1));
}

// ------------------------------------------------------- tf32 MMA GEMM -----
#define BM 64
#define BN 64
#define BKG 32
#define APAD 8
#define BPAD 8

__device__ __forceinline__ void gemm_tf32_body(
    const float* __restrict__ A, const float* __restrict__ B,
    const float* __restrict__ bias, float* __restrict__ C,
    int N, int K, int doRelu, int bm, int bn,
    float oscale, int roundOut)
{
    __shared__ float As[BKG][BM + APAD];   // [k][m]
    __shared__ float Bs[BKG][BN + BPAD];   // [k][n]

    const int tid  = threadIdx.x;
    const int warp = tid >> 5;
    const int lane = tid & 31;
    const int wm = (warp & 3) * 16;
    const int wn = (warp >> 2) * 32;
    const int g  = lane >> 2;
    const int tg = lane & 3;

    float acc[4][4];
#pragma unroll
    for (int i = 0; i < 4; i++)
#pragma unroll
        for (int j = 0; j < 4; j++) acc[i][j] = 0.f;

    const int ar0 = tid >> 3;
    const int ac0 = (tid & 7) * 4;
    const int br0 = tid >> 4;
    const int bc0 = (tid & 15) * 4;

    for (int k0 = 0; k0 < K; k0 += BKG) {
#pragma unroll
        for (int it = 0; it < 2; it++) {
            int arow = ar0 + it * 32;
            float4 av = *(const float4*)(A + (size_t)(bm + arow) * K + k0 + ac0);
            As[ac0 + 0][arow] = tf32r(av.x);
            As[ac0 + 1][arow] = tf32r(av.y);
            As[ac0 + 2][arow] = tf32r(av.z);
            As[ac0 + 3][arow] = tf32r(av.w);
            int brow = br0 + it * 16;
            float4 bv = *(const float4*)(B + (size_t)(k0 + brow) * N + bn + bc0);
            float4 bc;
            bc.x = tf32r(bv.x); bc.y = tf32r(bv.y);
            bc.z = tf32r(bv.z); bc.w = tf32r(bv.w);
            *(float4*)&Bs[brow][bc0] = bc;
        }
        __syncthreads();

#pragma unroll
        for (int ks = 0; ks < BKG; ks += 8) {
            uint32_t a0 = __float_as_uint(As[ks + tg    ][wm + g    ]);
            uint32_t a1 = __float_as_uint(As[ks + tg    ][wm + g + 8]);
            uint32_t a2 = __float_as_uint(As[ks + tg + 4][wm + g    ]);
            uint32_t a3 = __float_as_uint(As[ks + tg + 4][wm + g + 8]);
#pragma unroll
            for (int nt = 0; nt < 4; nt++) {
                uint32_t b0 = __float_as_uint(Bs[ks + tg    ][wn + nt * 8 + g]);
                uint32_t b1 = __float_as_uint(Bs[ks + tg + 4][wn + nt * 8 + g]);
                mma_tf32(acc[nt][0], acc[nt][1], acc[nt][2], acc[nt][3],
                         a0, a1, a2, a3, b0, b1);
            }
        }
        __syncthreads();
    }

    const int row0 = bm + wm + g;
    const int colb = bn + wn + 2 * tg;
#pragma unroll
    for (int nt = 0; nt < 4; nt++) {
        int col = colb + nt * 8;
        float b0v = 0.f, b1v = 0.f;
        if (bias) { b0v = bias[col]; b1v = bias[col + 1]; }
        float2 o0, o1;
        o0.x = acc[nt][0] * oscale + b0v; o0.y = acc[nt][1] * oscale + b1v;
        o1.x = acc[nt][2] * oscale + b0v; o1.y = acc[nt][3] * oscale + b1v;
        if (doRelu) {
            o0.x = fmaxf(o0.x, 0.f); o0.y = fmaxf(o0.y, 0.f);
            o1.x = fmaxf(o1.x, 0.f); o1.y = fmaxf(o1.y, 0.f);
        }
        if (roundOut) {
            o0.x = tf32r(o0.x); o0.y = tf32r(o0.y);
            o1.x = tf32r(o1.x); o1.y = tf32r(o1.y);
        }
        *(float2*)(C + (size_t)row0 * N + col)       = o0;
        *(float2*)(C + (size_t)(row0 + 8) * N + col) = o1;
    }
}

__global__ __launch_bounds__(256) void gemm_kernel(
    const float* __restrict__ A, const float* __restrict__ B,
    const float* __restrict__ bias, float* __restrict__ C,
    int N, int K, int doRelu)
{
    gemm_tf32_body(A, B, bias, C, N, K, doRelu,
                   blockIdx.y * BM, blockIdx.x * BN, 1.f, 0);
}

// fused QKV: z selects weight/output. Q output pre-scaled by QSCALE;
// Q,K,V all written tf32-rounded (consumed only by the mma attention).
__global__ __launch_bounds__(256) void gemm_qkv_kernel(
    const float* __restrict__ A,
    const float* __restrict__ Bq, const float* __restrict__ Bk,
    const float* __restrict__ Bv,
    float* __restrict__ Cq, float* __restrict__ Ck, float* __restrict__ Cv)
{
    const float* B = (blockIdx.z == 0) ? Bq : (blockIdx.z == 1) ? Bk : Bv;
    float*       C = (blockIdx.z == 0) ? Cq : (blockIdx.z == 1) ? Ck : Cv;
    float oscale = (blockIdx.z == 0) ? QSCALE : 1.f;
    gemm_tf32_body(A, B, nullptr, C, HH, HH, 0,
                   blockIdx.y * BM, blockIdx.x * BN, oscale, 1);
}

// ----------------------------------------------------- MMA Attention -------
// Block: 16 i-rows x 8 heads x 1 batch, j in 32-wide tiles. Warp w = head w.
// No online max (scores provably small; softmax shift-invariant, m=0).
// Scalar softmax runs on lanes 0..15 of each head's warp -> warp-local sync.
// K/V/rel staging register-prefetched one tile ahead.
#define TI 16
#define TJ 32
#define EPR 36      // EP row stride (i)
#define EPH 584     // EP head stride
#define KSR 260     // K tile row stride (j)
#define VSR 264     // V tile row stride (j)

// smem float offsets
#define SM_QREL 0                        // 128*101 = 12928
#define SM_EP   12928                    // 8*EPH   = 4672
#define SM_KS   17600                    // 32*260  = 8320 (Ev staged later)
#define SM_VS   25920                    // 32*264  = 8448
#define SM_RI   34368                    // 512 ints
#define SM_MK   34880                    // 512 ints
#define SM_CS   35392                    // 128 (row sums)
#define SM_W    35520                    // 128*101 = 12928
#define ATTN_SMEM_FLOATS 48448
#define ATTN_SMEM_BYTES  (ATTN_SMEM_FLOATS*4)   // 193792 B

__global__ __launch_bounds__(256, 1) void attn_kernel(
    const float* __restrict__ Q, const float* __restrict__ Kk,
    const float* __restrict__ V, const float* __restrict__ Ek,
    const float* __restrict__ Ev, const int* __restrict__ rel,
    const int* __restrict__ relmask, float* __restrict__ O)
{
    extern __shared__ float sm[];
    float* QREL = sm + SM_QREL;
    float* EP   = sm + SM_EP;
    float* Ks   = sm + SM_KS;
    float* Vs   = sm + SM_VS;
    int*   ri   = (int*)(sm + SM_RI);
    int*   mk   = (int*)(sm + SM_MK);
    float* Cs   = sm + SM_CS;
    float* Wh   = sm + SM_W;

    const int tid  = threadIdx.x;
    const int b    = blockIdx.y;
    const int i0   = blockIdx.x * TI;
    const int row0 = b * LL + i0;
    const int w    = tid >> 5;
    const int lane = tid & 31;
    const int g    = lane >> 2;
    const int tg   = lane & 3;

    // ---- QREL precompute: qrel[pr][r] = q_scaled(pr) . Ek[r] ----
    {
        const int pr = tid & 127;
        const int h  = pr >> 4, il = pr & 15;
        float ql[32];
        const float4* qp = (const float4*)(Q + (size_t)(row0 + il) * HH + h * DHEAD);
#pragma unroll
        for (int d4 = 0; d4 < 8; d4++) {
            float4 v4 = qp[d4];
            ql[d4*4+0] = v4.x; ql[d4*4+1] = v4.y;
            ql[d4*4+2] = v4.z; ql[d4*4+3] = v4.w;
        }
        float* qrow = QREL + pr * 101;
        const int r0 = (tid >> 7) * 50;
#pragma unroll 2
        for (int r = r0; r < r0 + 50; r++) {
            const float4* e4 = (const float4*)(Ek + r * 32);
            float d0 = 0.f, d1 = 0.f, d2 = 0.f, d3 = 0.f;
#pragma unroll
            for (int d4 = 0; d4 < 8; d4++) {
                float4 ev = e4[d4];
                d0 += ql[d4*4+0] * ev.x; d1 += ql[d4*4+1] * ev.y;
                d2 += ql[d4*4+2] * ev.z; d3 += ql[d4*4+3] * ev.w;
            }
            qrow[r] = (d0 + d1) + (d2 + d3);
        }
    }

    // ---- stage Q (scaled+tf32) into EP region ----
#pragma unroll
    for (int q = 0; q < 4; q++) {
        int f  = tid + q * 256;
        int i  = f >> 6;
        int hc = f & 63;
        int hh = hc >> 3, d4 = hc & 7;
        float4 v4 = ((const float4*)Q)[(size_t)(row0 + i) * 64 + hc];
        *(float4*)&EP[hh * EPH + i * EPR + d4 * 4] = v4;
    }

    // ---- zero relation histogram ----
    if (tid < 128) {
        float* wrp0 = Wh + tid * 101;
#pragma unroll 4
        for (int r = 0; r < RELN; r++) wrp0[r] = 0.f;
    }
    __syncthreads();

    // ---- preload Q fragments ----
    uint32_t qa[4][4];
    {
        const float* eph = EP + w * EPH;
#pragma unroll
        for (int ks = 0; ks < 4; ks++) {
            qa[ks][0] = __float_as_uint(eph[ g      * EPR + tg     + 8*ks]);
            qa[ks][1] = __float_as_uint(eph[(g + 8) * EPR + tg     + 8*ks]);
            qa[ks][2] = __float_as_uint(eph[ g      * EPR + tg + 4 + 8*ks]);
            qa[ks][3] = __float_as_uint(eph[(g + 8) * EPR + tg + 4 + 8*ks]);
        }
    }

    const float4* kg4 = (const float4*)Kk;
    const float4* vg4 = (const float4*)V;

    // ---- stage tile 0 ----
#pragma unroll
    for (int q = 0; q < 8; q++) {
        int f  = tid + q * 256;
        int jj = f >> 6;
        int c4 = f & 63;
        int gi = (b * LL + jj) * 64 + c4;
        *(float4*)&Ks[jj * KSR + c4 * 4] = kg4[gi];
        *(float4*)&Vs[jj * VSR + c4 * 4] = vg4[gi];
    }
#pragma unroll
    for (int q = 0; q < 2; q++) {
        int f  = tid + q * 256;
        int ii = f >> 5, jj = f & 31;
        size_t gi = (size_t)(row0 + ii) * LL + jj;
        ri[ii * 32 + jj] = rel[gi];
        mk[ii * 32 + jj] = relmask[gi];
    }
    __syncthreads();

    float s = 0.f;
    float oa[4][4];
#pragma unroll
    for (int ns = 0; ns < 4; ns++)
#pragma unroll
        for (int c = 0; c < 4; c++) oa[ns][c] = 0.f;

    const int srow   = w * 16 + (lane & 15);     // scalar row (h, il)
    float* qrow_s    = QREL + srow * 101;
    float* wrp       = Wh   + srow * 101;

    const int NT = LL / TJ;
    for (int t = 0; t < NT; t++) {
        // ---- prefetch next tile into registers ----
        float4 kpre[8], vpre[8];
        int rpre[2], mpre[2];
        if (t + 1 < NT) {
            const int j0n = (t + 1) * TJ;
#pragma unroll
            for (int q = 0; q < 8; q++) {
                int f  = tid + q * 256;
                int jj = f >> 6;
                int c4 = f & 63;
                int gi = (b * LL + j0n + jj) * 64 + c4;
                kpre[q] = kg4[gi];
                vpre[q] = vg4[gi];
            }
#pragma unroll
            for (int q = 0; q < 2; q++) {
                int f  = tid + q * 256;
                int ii = f >> 5, jj = f & 31;
                size_t gi = (size_t)(row0 + ii) * LL + j0n + jj;
                rpre[q] = rel[gi];
                mpre[q] = relmask[gi];
            }
        }

        // ---- score MMA: e(16x32) = Q . K^T ----
        {
            float* eph = EP + w * EPH;
            const float* ksh = Ks + w * 32;
#pragma unroll
            for (int ns = 0; ns < 4; ns++) {
                float e0 = 0.f, e1 = 0.f, e2 = 0.f, e3 = 0.f;
                const float* kb = ksh + (ns * 8 + g) * KSR;
#pragma unroll
                for (int ks = 0; ks < 4; ks++) {
                    uint32_t b0 = __float_as_uint(kb[tg     + 8*ks]);
                    uint32_t b1 = __float_as_uint(kb[tg + 4 + 8*ks]);
                    mma_tf32(e0, e1, e2, e3,
                             qa[ks][0], qa[ks][1], qa[ks][2], qa[ks][3], b0, b1);
                }
                *(float2*)&eph[ g      * EPR + ns * 8 + 2*tg] = make_float2(e0, e1);
                *(float2*)&eph[(g + 8) * EPR + ns * 8 + 2*tg] = make_float2(e2, e3);
            }
        }
        __syncwarp();

        // ---- scalar softmax (lanes 0..15 of each warp; fixed m=0) ----
        if (lane < 16) {
            float* erow = EP + w * EPH + lane * EPR;
            const int* rr   = ri + lane * 32;
            const int* mrow = mk + lane * 32;
            float ss = 0.f;
#pragma unroll 8
            for (int jj = 0; jj < TJ; jj++) {
                int r = rr[jj];
                float e = erow[jj] + qrow_s[r];
                float p = mrow[jj] ? 0.f : ex2f(e);
                ss += p;
                wrp[r] += p;
                erow[jj] = tf32r(p);
            }
            s += ss;
        }
        __syncwarp();

        // ---- AV MMA: o += P(16x32) . V(32x32) ----
        {
            const float* eph = EP + w * EPH;
#pragma unroll
            for (int ks = 0; ks < 4; ks++) {
                uint32_t pa0 = __float_as_uint(eph[ g      * EPR + tg     + 8*ks]);
                uint32_t pa1 = __float_as_uint(eph[(g + 8) * EPR + tg     + 8*ks]);
                uint32_t pa2 = __float_as_uint(eph[ g      * EPR + tg + 4 + 8*ks]);
                uint32_t pa3 = __float_as_uint(eph[(g + 8) * EPR + tg + 4 + 8*ks]);
                const float* vb0 = Vs + (ks * 8 + tg    ) * VSR + w * 32;
                const float* vb1 = Vs + (ks * 8 + tg + 4) * VSR + w * 32;
#pragma unroll
                for (int ns = 0; ns < 4; ns++) {
                    uint32_t b0 = __float_as_uint(vb0[ns * 8 + g]);
                    uint32_t b1 = __float_as_uint(vb1[ns * 8 + g]);
                    mma_tf32(oa[ns][0], oa[ns][1], oa[ns][2], oa[ns][3],
                             pa0, pa1, pa2, pa3, b0, b1);
                }
            }
        }
        __syncthreads();   // all warps done reading tile t

        if (t + 1 < NT) {
            // ---- commit prefetched tile t+1 ----
#pragma unroll
            for (int q = 0; q < 8; q++) {
                int f  = tid + q * 256;
                int jj = f >> 6;
                int c4 = f & 63;
                *(float4*)&Ks[jj * KSR + c4 * 4] = kpre[q];
                *(float4*)&Vs[jj * VSR + c4 * 4] = vpre[q];
            }
#pragma unroll
            for (int q = 0; q < 2; q++) {
                int f  = tid + q * 256;
                int ii = f >> 5, jj = f & 31;
                ri[ii * 32 + jj] = rpre[q];
                mk[ii * 32 + jj] = mpre[q];
            }
            __syncthreads();
        }
    }

    // ---- epilogue: o frags + row sums -> smem ----
    {
        float* eph = EP + w * EPH;
#pragma unroll
        for (int ns = 0; ns < 4; ns++) {
            *(float2*)&eph[ g      * EPR + ns * 8 + 2*tg] = make_float2(oa[ns][0], oa[ns][1]);
            *(float2*)&eph[(g + 8) * EPR + ns * 8 + 2*tg] = make_float2(oa[ns][2], oa[ns][3]);
        }
        if (lane < 16) Cs[srow] = s;
    }
    // stage Ev into Ks region
    for (int f = tid; f < RELN * 32; f += 256) Ks[f] = Ev[f];
    __syncthreads();

    if (tid < 128) {
        const int h = tid >> 4, il = tid & 15;
        const float* orow = EP + h * EPH + il * EPR;
        const float* wrd  = Wh + tid * 101;
        float of[32];
#pragma unroll
        for (int d = 0; d < 32; d++) of[d] = orow[d];
#pragma unroll 2
        for (int r = 0; r < RELN; r++) {
            float wv = wrd[r];
            const float4* ev4 = (const float4*)(Ks + r * 32);
#pragma unroll
            for (int d4 = 0; d4 < 8; d4++) {
                float4 ev = ev4[d4];
                of[d4*4+0] += wv * ev.x; of[d4*4+1] += wv * ev.y;
                of[d4*4+2] += wv * ev.z; of[d4*4+3] += wv * ev.w;
            }
        }
        float inv = 1.f / Cs[tid];
        float* op = O + (size_t)(row0 + il) * HH + h * 32;
#pragma unroll
        for (int d4 = 0; d4 < 8; d4++) {
            float4 v4;
            v4.x = of[d4*4+0] * inv; v4.y = of[d4*4+1] * inv;
            v4.z = of[d4*4+2] * inv; v4.w = of[d4*4+3] * inv;
            *(float4*)(op + d4 * 4) = v4;
        }
    }
}

// ------------------------------------------------- Residual + LayerNorm ----
__global__ __launch_bounds__(256) void ln_kernel(
    const float* __restrict__ X, const float* __restrict__ Y,
    const float* __restrict__ g, const float* __restrict__ bta,
    float* __restrict__ Out)
{
    const int r = blockIdx.x;
    const int c = threadIdx.x;
    float v = X[(size_t)r * HH + c] + Y[(size_t)r * HH + c];
    float s1 = v, s2 = v * v;
#pragma unroll
    for (int o = 16; o; o >>= 1) {
        s1 += __shfl_xor_sync(0xffffffffu, s1, o);
        s2 += __shfl_xor_sync(0xffffffffu, s2, o);
    }
    __shared__ float r1[8], r2[8];
    if ((c & 31) == 0) { r1[c >> 5] = s1; r2[c >> 5] = s2; }
    __syncthreads();
    if (c < 32) {
        s1 = (c < 8) ? r1[c] : 0.f;
        s2 = (c < 8) ? r2[c] : 0.f;
#pragma unroll
        for (int o = 4; o; o >>= 1) {
            s1 += __shfl_xor_sync(0xffffffffu, s1, o);
            s2 += __shfl_xor_sync(0xffffffffu, s2, o);
        }
        if (c == 0) { r1[0] = s1; r2[0] = s2; }
    }
    __syncthreads();
    float mean = r1[0] * (1.f / HH);
    float var  = r2[0] * (1.f / HH) - mean * mean;
    Out[(size_t)r * HH + c] = (v - mean) * rsqrtf(var + EPSLN) * g[c] + bta[c];
}

// ------------------------------------------------------------- launcher ----
extern "C" void kernel_launch(void* const* d_in, const int* in_sizes, int n_in,
                              void* d_out, int out_size)
{
    const float* inputs = (const float*)d_in[0];
    const float* Wq  = (const float*)d_in[1];
    const float* Wk  = (const float*)d_in[2];
    const float* Wv  = (const float*)d_in[3];
    const float* Wo  = (const float*)d_in[4];
    const float* bo  = (const float*)d_in[5];
    const float* W1  = (const float*)d_in[6];
    const float* b1  = (const float*)d_in[7];
    const float* W2  = (const float*)d_in[8];
    const float* b2  = (const float*)d_in[9];
    const float* ln1g = (const float*)d_in[10];
    const float* ln1b = (const float*)d_in[11];
    const float* ln2g = (const float*)d_in[12];
    const float* ln2b = (const float*)d_in[13];
    const float* Ek  = (const float*)d_in[14];
    const float* Ev  = (const float*)d_in[15];
    const int*   rel = (const int*)d_in[16];
    const int*   rmask = (const int*)d_in[17];
    float* out = (float*)d_out;

    float *qb, *kb, *vb, *ab, *yb, *xb, *fb;
    cudaGetSymbolAddress((void**)&qb, g_qb);
    cudaGetSymbolAddress((void**)&kb, g_kb);
    cudaGetSymbolAddress((void**)&vb, g_vb);
    cudaGetSymbolAddress((void**)&ab, g_ab);
    cudaGetSymbolAddress((void**)&yb, g_yb);
    cudaGetSymbolAddress((void**)&xb, g_xb);
    cudaGetSymbolAddress((void**)&fb, g_fb);

    cudaFuncSetAttribute(attn_kernel,
                         cudaFuncAttributeMaxDynamicSharedMemorySize,
                         ATTN_SMEM_BYTES);

    for (int l = 0; l < NLAYER; l++) {
        const float* x = (l == 0) ? inputs : xb;
        const size_t wHH = (size_t)l * HH * HH;
        const size_t wHF = (size_t)l * HH * FFD;

        gemm_qkv_kernel<<<dim3(HH/BN, ROWS/BM, 3), 256>>>(
            x, Wq + wHH, Wk + wHH, Wv + wHH, qb, kb, vb);

        attn_kernel<<<dim3(LL/TI, BB), 256, ATTN_SMEM_BYTES>>>(qb, kb, vb, Ek, Ev, rel, rmask, ab);

        gemm_kernel<<<dim3(HH/BN, ROWS/BM), 256>>>(ab, Wo + wHH, bo + l*HH, yb, HH, HH, 0);
        ln_kernel<<<ROWS, HH>>>(x, yb, ln1g + l*HH, ln1b + l*HH, xb);

        gemm_kernel<<<dim3(FFD/BN, ROWS/BM), 256>>>(xb, W1 + wHF, b1 + l*FFD, fb, FFD, HH, 1);
        gemm_kernel<<<dim3(HH/BN, ROWS/BM), 256>>>(fb, W2 + wHF, b2 + l*HH, yb, HH, FFD, 0);
        ln_kernel<<<ROWS, HH>>>(xb, yb, ln2g + l*HH, ln2b + l*HH, (l == NLAYER-1) ? out : xb);
    }
}